// round 3
// baseline (speedup 1.0000x reference)
#include <cuda_runtime.h>
#include <math.h>

#define B_     8
#define N_     10000
#define D_     16
#define E_     320000
#define EH_    32
#define EOUT_  30
#define EOUTP_ 32   // padded agg row (128B-aligned for v4 reductions)
#define NOUT_  64
#define ITEMS_ 4    // batch-items per thread (same edge, 4 consecutive batches)

// ---------------- device scratch (no allocations allowed) ----------------
__device__ double g_stats[4];                        // sum0, sum1, sumsq0, sumsq1
__device__ float  g_norm[4];                         // mean0, mean1, rstd0, rstd1
__device__ __align__(16) float g_agg[B_ * N_ * EOUTP_];  // 10.24 MB padded agg

__device__ __forceinline__ float sigmoidf(float v) {
    return 1.0f / (1.0f + __expf(-v));
}

__device__ __forceinline__ void red_v4(float* p, float a, float b, float c, float d) {
    asm volatile("red.global.add.v4.f32 [%0], {%1, %2, %3, %4};"
                 :: "l"(p), "f"(a), "f"(b), "f"(c), "f"(d) : "memory");
}
__device__ __forceinline__ void red_v2(float* p, float a, float b) {
    asm volatile("red.global.add.v2.f32 [%0], {%1, %2};"
                 :: "l"(p), "f"(a), "f"(b) : "memory");
}

__device__ __forceinline__ float f4get(const float4& v, int k) {
    return k == 0 ? v.x : (k == 1 ? v.y : (k == 2 ? v.z : v.w));
}

// ---------------- zero scratch ----------------
__global__ void zero_kernel() {
    const int total4 = (B_ * N_ * EOUTP_) / 4;
    float4 z = make_float4(0.f, 0.f, 0.f, 0.f);
    for (int i = blockIdx.x * blockDim.x + threadIdx.x; i < total4;
         i += gridDim.x * blockDim.x) {
        ((float4*)g_agg)[i] = z;
    }
    if (blockIdx.x == 0 && threadIdx.x < 4) g_stats[threadIdx.x] = 0.0;
}

// ---------------- edge_attr mean/std reduction (double precision) ----------------
__global__ void stats_kernel(const float* __restrict__ ea) {
    double s0 = 0.0, s1 = 0.0, q0 = 0.0, q1 = 0.0;
    for (int i = blockIdx.x * blockDim.x + threadIdx.x; i < E_;
         i += gridDim.x * blockDim.x) {
        float a = ea[2 * i];
        float b = ea[2 * i + 1];
        s0 += (double)a;
        s1 += (double)b;
        q0 += (double)a * (double)a;
        q1 += (double)b * (double)b;
    }
    for (int o = 16; o > 0; o >>= 1) {
        s0 += __shfl_down_sync(0xffffffffu, s0, o);
        s1 += __shfl_down_sync(0xffffffffu, s1, o);
        q0 += __shfl_down_sync(0xffffffffu, q0, o);
        q1 += __shfl_down_sync(0xffffffffu, q1, o);
    }
    if ((threadIdx.x & 31) == 0) {
        atomicAdd(&g_stats[0], s0);
        atomicAdd(&g_stats[1], s1);
        atomicAdd(&g_stats[2], q0);
        atomicAdd(&g_stats[3], q1);
    }
}

__global__ void finalize_kernel() {
    if (threadIdx.x == 0 && blockIdx.x == 0) {
        const double n = (double)E_;
        double v0 = (g_stats[2] - g_stats[0] * g_stats[0] / n) / (n - 1.0);
        double v1 = (g_stats[3] - g_stats[1] * g_stats[1] / n) / (n - 1.0);
        g_norm[0] = (float)(g_stats[0] / n);
        g_norm[1] = (float)(g_stats[1] / n);
        g_norm[2] = (float)(1.0 / sqrt(v0));
        g_norm[3] = (float)(1.0 / sqrt(v1));
    }
}

// ---------------- edge MLP + scatter: 4 batch-items per thread ----------------
__global__ void __launch_bounds__(128) edge_kernel(
    const float* __restrict__ x, const int* __restrict__ ei,
    const float* __restrict__ ea,
    const float* __restrict__ wm, const float* __restrict__ ws,
    const float* __restrict__ W1, const float* __restrict__ b1,
    const float* __restrict__ W2, const float* __restrict__ b2)
{
    __shared__ __align__(16) float sW1[35 * EH_];       // [35][32]
    __shared__ __align__(16) float sW2t[EOUT_ * EH_];   // transposed [30][32]
    __shared__ float sb1[EH_];
    __shared__ float sb2[EOUT_];

    for (int i = threadIdx.x; i < 35 * EH_; i += blockDim.x) sW1[i] = W1[i];
    for (int i = threadIdx.x; i < EH_ * EOUT_; i += blockDim.x) {
        int j = i / EOUT_;
        int c = i % EOUT_;
        sW2t[c * EH_ + j] = W2[i];
    }
    if (threadIdx.x < EH_)   sb1[threadIdx.x] = b1[threadIdx.x];
    if (threadIdx.x < EOUT_) sb2[threadIdx.x] = b2[threadIdx.x];
    __syncthreads();

    unsigned gid = blockIdx.x * blockDim.x + threadIdx.x;
    if (gid >= (unsigned)E_ * 2u) return;
    int e  = gid >> 1;            // edge id
    int g  = gid & 1;             // batch group: batches 4g..4g+3
    int src = ei[e];
    int tgt = ei[E_ + e];

    const float4* ps[ITEMS_];
    const float4* pt[ITEMS_];
#pragma unroll
    for (int m = 0; m < ITEMS_; m++) {
        int b = 4 * g + m;
        ps[m] = (const float4*)(x + (size_t)(b * N_ + src) * D_);
        pt[m] = (const float4*)(x + (size_t)(b * N_ + tgt) * D_);
    }

    // edge-shared scalars
    float cd   = ea[2 * e];
    float cdi  = ea[2 * e + 1];
    float ean0 = (cd  - g_norm[0]) * g_norm[2];
    float ean1 = (cdi - g_norm[1]) * g_norm[3];
    float wm0 = wm[0], wm1 = wm[1], ws0 = ws[0], ws1 = ws[1];

    // hidden accumulators
    float h[ITEMS_][EH_];
#pragma unroll
    for (int jj = 0; jj < 8; jj++) {
        float4 bv = ((const float4*)sb1)[jj];
#pragma unroll
        for (int m = 0; m < ITEMS_; m++) {
            h[m][4 * jj + 0] = bv.x;
            h[m][4 * jj + 1] = bv.y;
            h[m][4 * jj + 2] = bv.z;
            h[m][4 * jj + 3] = bv.w;
        }
    }

    float spd[ITEMS_], dir[ITEMS_];

    // ---- layer 1: src features (rows 0..15) ----
#pragma unroll
    for (int q = 0; q < 4; q++) {
        float4 f[ITEMS_];
#pragma unroll
        for (int m = 0; m < ITEMS_; m++) f[m] = ps[m][q];
        if (q == 3) {
#pragma unroll
            for (int m = 0; m < ITEMS_; m++) {
                spd[m] = fmaf(f[m].z, ws0, wm0);   // xs[14]
                dir[m] = fmaf(f[m].w, ws1, wm1);   // xs[15]
            }
        }
#pragma unroll
        for (int kk = 0; kk < 4; kk++) {
            const float4* w = (const float4*)(sW1 + (4 * q + kk) * EH_);
#pragma unroll
            for (int jj = 0; jj < 8; jj++) {
                float4 v = w[jj];
#pragma unroll
                for (int m = 0; m < ITEMS_; m++) {
                    float s = f4get(f[m], kk);
                    h[m][4 * jj + 0] = fmaf(s, v.x, h[m][4 * jj + 0]);
                    h[m][4 * jj + 1] = fmaf(s, v.y, h[m][4 * jj + 1]);
                    h[m][4 * jj + 2] = fmaf(s, v.z, h[m][4 * jj + 2]);
                    h[m][4 * jj + 3] = fmaf(s, v.w, h[m][4 * jj + 3]);
                }
            }
        }
    }

    // ---- layer 1: tgt features (rows 16..31) ----
#pragma unroll
    for (int q = 0; q < 4; q++) {
        float4 f[ITEMS_];
#pragma unroll
        for (int m = 0; m < ITEMS_; m++) f[m] = pt[m][q];
#pragma unroll
        for (int kk = 0; kk < 4; kk++) {
            const float4* w = (const float4*)(sW1 + (16 + 4 * q + kk) * EH_);
#pragma unroll
            for (int jj = 0; jj < 8; jj++) {
                float4 v = w[jj];
#pragma unroll
                for (int m = 0; m < ITEMS_; m++) {
                    float s = f4get(f[m], kk);
                    h[m][4 * jj + 0] = fmaf(s, v.x, h[m][4 * jj + 0]);
                    h[m][4 * jj + 1] = fmaf(s, v.y, h[m][4 * jj + 1]);
                    h[m][4 * jj + 2] = fmaf(s, v.z, h[m][4 * jj + 2]);
                    h[m][4 * jj + 3] = fmaf(s, v.w, h[m][4 * jj + 3]);
                }
            }
        }
    }

    // ---- layer 1: extra rows 32 (ean0), 33 (ean1), 34 (ewt per item) ----
    {
        const float4* w32 = (const float4*)(sW1 + 32 * EH_);
        const float4* w33 = (const float4*)(sW1 + 33 * EH_);
        const float4* w34 = (const float4*)(sW1 + 34 * EH_);
        float ewt[ITEMS_];
#pragma unroll
        for (int m = 0; m < ITEMS_; m++) {
            float theta = fabsf(cdi - dir[m]);
            ewt[m] = fmaxf(0.0f, 3.0f * spd[m] * __cosf(theta) / cd);
        }
#pragma unroll
        for (int jj = 0; jj < 8; jj++) {
            float4 v0 = w32[jj];
            float4 v1 = w33[jj];
            float4 v2 = w34[jj];
#pragma unroll
            for (int m = 0; m < ITEMS_; m++) {
                float a0 = fmaf(ean0, v0.x, fmaf(ean1, v1.x, ewt[m] * v2.x));
                float a1 = fmaf(ean0, v0.y, fmaf(ean1, v1.y, ewt[m] * v2.y));
                float a2 = fmaf(ean0, v0.z, fmaf(ean1, v1.z, ewt[m] * v2.z));
                float a3 = fmaf(ean0, v0.w, fmaf(ean1, v1.w, ewt[m] * v2.w));
                h[m][4 * jj + 0] += a0;
                h[m][4 * jj + 1] += a1;
                h[m][4 * jj + 2] += a2;
                h[m][4 * jj + 3] += a3;
            }
        }
    }

    // sigmoid
#pragma unroll
    for (int m = 0; m < ITEMS_; m++)
#pragma unroll
        for (int j = 0; j < EH_; j++) h[m][j] = sigmoidf(h[m][j]);

    // ---- layer 2 + scatter ----
    float* at[ITEMS_];
    float* as[ITEMS_];
#pragma unroll
    for (int m = 0; m < ITEMS_; m++) {
        int b = 4 * g + m;
        at[m] = g_agg + (size_t)(b * N_ + tgt) * EOUTP_;
        as[m] = g_agg + (size_t)(b * N_ + src) * EOUTP_;
    }

#pragma unroll
    for (int c4 = 0; c4 < 7; c4++) {
        int o0 = 4 * c4;
        float acc[ITEMS_][4];
#pragma unroll
        for (int m = 0; m < ITEMS_; m++) {
            acc[m][0] = sb2[o0 + 0];
            acc[m][1] = sb2[o0 + 1];
            acc[m][2] = sb2[o0 + 2];
            acc[m][3] = sb2[o0 + 3];
        }
#pragma unroll
        for (int jj = 0; jj < 8; jj++) {
            float4 w0 = ((const float4*)(sW2t + (o0 + 0) * EH_))[jj];
            float4 w1 = ((const float4*)(sW2t + (o0 + 1) * EH_))[jj];
            float4 w2 = ((const float4*)(sW2t + (o0 + 2) * EH_))[jj];
            float4 w3 = ((const float4*)(sW2t + (o0 + 3) * EH_))[jj];
#pragma unroll
            for (int m = 0; m < ITEMS_; m++) {
                float h0 = h[m][4 * jj + 0], h1 = h[m][4 * jj + 1];
                float h2 = h[m][4 * jj + 2], h3 = h[m][4 * jj + 3];
                acc[m][0] = fmaf(h0, w0.x, acc[m][0]);
                acc[m][0] = fmaf(h1, w0.y, acc[m][0]);
                acc[m][0] = fmaf(h2, w0.z, acc[m][0]);
                acc[m][0] = fmaf(h3, w0.w, acc[m][0]);
                acc[m][1] = fmaf(h0, w1.x, acc[m][1]);
                acc[m][1] = fmaf(h1, w1.y, acc[m][1]);
                acc[m][1] = fmaf(h2, w1.z, acc[m][1]);
                acc[m][1] = fmaf(h3, w1.w, acc[m][1]);
                acc[m][2] = fmaf(h0, w2.x, acc[m][2]);
                acc[m][2] = fmaf(h1, w2.y, acc[m][2]);
                acc[m][2] = fmaf(h2, w2.z, acc[m][2]);
                acc[m][2] = fmaf(h3, w2.w, acc[m][2]);
                acc[m][3] = fmaf(h0, w3.x, acc[m][3]);
                acc[m][3] = fmaf(h1, w3.y, acc[m][3]);
                acc[m][3] = fmaf(h2, w3.z, acc[m][3]);
                acc[m][3] = fmaf(h3, w3.w, acc[m][3]);
            }
        }
#pragma unroll
        for (int m = 0; m < ITEMS_; m++) {
            float e0 = sigmoidf(acc[m][0]);
            float e1 = sigmoidf(acc[m][1]);
            float e2 = sigmoidf(acc[m][2]);
            float e3 = sigmoidf(acc[m][3]);
            red_v4(at[m] + o0,  e0,  e1,  e2,  e3);
            red_v4(as[m] + o0, -e0, -e1, -e2, -e3);
        }
    }
    // tail outputs 28, 29
    {
        float acc[ITEMS_][2];
#pragma unroll
        for (int m = 0; m < ITEMS_; m++) {
            acc[m][0] = sb2[28];
            acc[m][1] = sb2[29];
        }
#pragma unroll
        for (int jj = 0; jj < 8; jj++) {
            float4 w0 = ((const float4*)(sW2t + 28 * EH_))[jj];
            float4 w1 = ((const float4*)(sW2t + 29 * EH_))[jj];
#pragma unroll
            for (int m = 0; m < ITEMS_; m++) {
                float h0 = h[m][4 * jj + 0], h1 = h[m][4 * jj + 1];
                float h2 = h[m][4 * jj + 2], h3 = h[m][4 * jj + 3];
                acc[m][0] = fmaf(h0, w0.x, acc[m][0]);
                acc[m][0] = fmaf(h1, w0.y, acc[m][0]);
                acc[m][0] = fmaf(h2, w0.z, acc[m][0]);
                acc[m][0] = fmaf(h3, w0.w, acc[m][0]);
                acc[m][1] = fmaf(h0, w1.x, acc[m][1]);
                acc[m][1] = fmaf(h1, w1.y, acc[m][1]);
                acc[m][1] = fmaf(h2, w1.z, acc[m][1]);
                acc[m][1] = fmaf(h3, w1.w, acc[m][1]);
            }
        }
#pragma unroll
        for (int m = 0; m < ITEMS_; m++) {
            float e0 = sigmoidf(acc[m][0]);
            float e1 = sigmoidf(acc[m][1]);
            red_v2(at[m] + 28,  e0,  e1);
            red_v2(as[m] + 28, -e0, -e1);
        }
    }
}

// ---------------- node MLP ----------------
__global__ void __launch_bounds__(256) node_kernel(
    const float* __restrict__ Wn, const float* __restrict__ bn,
    float* __restrict__ out)
{
    __shared__ __align__(16) float sWn[EOUT_ * NOUT_];
    __shared__ float sbn[NOUT_];
    for (int i = threadIdx.x; i < EOUT_ * NOUT_; i += blockDim.x) sWn[i] = Wn[i];
    if (threadIdx.x < NOUT_) sbn[threadIdx.x] = bn[threadIdx.x];
    __syncthreads();

    int node = blockIdx.x * blockDim.x + threadIdx.x;  // flattened (b, n)
    if (node >= B_ * N_) return;

    float a[EOUT_];
    const float4* ag = (const float4*)(g_agg + (size_t)node * EOUTP_);
#pragma unroll
    for (int q = 0; q < 7; q++) {
        float4 v = ag[q];
        a[4 * q + 0] = v.x; a[4 * q + 1] = v.y;
        a[4 * q + 2] = v.z; a[4 * q + 3] = v.w;
    }
    {
        float4 v = ag[7];
        a[28] = v.x; a[29] = v.y;  // ignore padding .z/.w
    }

    float* op = out + (size_t)node * NOUT_;
#pragma unroll
    for (int o = 0; o < NOUT_; o += 8) {
        float acc[8];
#pragma unroll
        for (int t = 0; t < 8; t++) acc[t] = sbn[o + t];
#pragma unroll
        for (int j = 0; j < EOUT_; j++) {
            float4 w0 = *(const float4*)(sWn + j * NOUT_ + o);
            float4 w1 = *(const float4*)(sWn + j * NOUT_ + o + 4);
            acc[0] = fmaf(a[j], w0.x, acc[0]);
            acc[1] = fmaf(a[j], w0.y, acc[1]);
            acc[2] = fmaf(a[j], w0.z, acc[2]);
            acc[3] = fmaf(a[j], w0.w, acc[3]);
            acc[4] = fmaf(a[j], w1.x, acc[4]);
            acc[5] = fmaf(a[j], w1.y, acc[5]);
            acc[6] = fmaf(a[j], w1.z, acc[6]);
            acc[7] = fmaf(a[j], w1.w, acc[7]);
        }
        float4 r0 = make_float4(sigmoidf(acc[0]), sigmoidf(acc[1]),
                                sigmoidf(acc[2]), sigmoidf(acc[3]));
        float4 r1 = make_float4(sigmoidf(acc[4]), sigmoidf(acc[5]),
                                sigmoidf(acc[6]), sigmoidf(acc[7]));
        *(float4*)(op + o)     = r0;
        *(float4*)(op + o + 4) = r1;
    }
}

// ---------------- launch ----------------
extern "C" void kernel_launch(void* const* d_in, const int* in_sizes, int n_in,
                              void* d_out, int out_size) {
    const float* x  = (const float*)d_in[0];
    const int*   ei = (const int*)d_in[1];
    const float* ea = (const float*)d_in[2];
    const float* wm = (const float*)d_in[3];
    const float* ws = (const float*)d_in[4];
    const float* W1 = (const float*)d_in[5];
    const float* b1 = (const float*)d_in[6];
    const float* W2 = (const float*)d_in[7];
    const float* b2 = (const float*)d_in[8];
    const float* Wn = (const float*)d_in[9];
    const float* bn = (const float*)d_in[10];
    float* out = (float*)d_out;

    zero_kernel<<<512, 256>>>();
    stats_kernel<<<256, 256>>>(ea);
    finalize_kernel<<<1, 32>>>();
    edge_kernel<<<(E_ * 2) / 128, 128>>>(x, ei, ea, wm, ws, W1, b1, W2, b2);
    node_kernel<<<(B_ * N_ + 255) / 256, 256>>>(Wn, bn, out);
}

// round 4
// speedup vs baseline: 1.7740x; 1.7740x over previous
#include <cuda_runtime.h>
#include <math.h>

#define B_     8
#define N_     10000
#define D_     16
#define E_     320000
#define EH_    32
#define EOUT_  30
#define EOUTP_ 32   // padded agg row (128B-aligned for v4 reductions)
#define NOUT_  64

// ---------------- constant-memory weights (uniform-port LDCU, off the L1 pipe) ----
__constant__ float c_W1[35 * EH_];
__constant__ float c_b1[EH_];
__constant__ float c_W2[EH_ * EOUT_];
__constant__ float c_b2[EOUT_];
__constant__ float c_Wn[EOUT_ * NOUT_];
__constant__ float c_bn[NOUT_];
__constant__ float c_wind[4];   // wm0, wm1, ws0, ws1

// ---------------- device scratch (no allocations allowed) ----------------
__device__ double g_stats[4];                        // sum0, sum1, sumsq0, sumsq1
__device__ float  g_norm[4];                         // mean0, mean1, rstd0, rstd1
__device__ __align__(16) float g_agg[B_ * N_ * EOUTP_];  // 10.24 MB padded agg

__device__ __forceinline__ float sigmoidf(float v) {
    return 1.0f / (1.0f + __expf(-v));
}

__device__ __forceinline__ void red_v4(float* p, float a, float b, float c, float d) {
    asm volatile("red.global.add.v4.f32 [%0], {%1, %2, %3, %4};"
                 :: "l"(p), "f"(a), "f"(b), "f"(c), "f"(d) : "memory");
}
__device__ __forceinline__ void red_v2(float* p, float a, float b) {
    asm volatile("red.global.add.v2.f32 [%0], {%1, %2};"
                 :: "l"(p), "f"(a), "f"(b) : "memory");
}

// ---------------- zero scratch ----------------
__global__ void zero_kernel() {
    const int total4 = (B_ * N_ * EOUTP_) / 4;
    float4 z = make_float4(0.f, 0.f, 0.f, 0.f);
    for (int i = blockIdx.x * blockDim.x + threadIdx.x; i < total4;
         i += gridDim.x * blockDim.x) {
        ((float4*)g_agg)[i] = z;
    }
    if (blockIdx.x == 0 && threadIdx.x < 4) g_stats[threadIdx.x] = 0.0;
}

// ---------------- edge_attr mean/std reduction (double precision) ----------------
__global__ void stats_kernel(const float* __restrict__ ea) {
    double s0 = 0.0, s1 = 0.0, q0 = 0.0, q1 = 0.0;
    for (int i = blockIdx.x * blockDim.x + threadIdx.x; i < E_;
         i += gridDim.x * blockDim.x) {
        float a = ea[2 * i];
        float b = ea[2 * i + 1];
        s0 += (double)a;
        s1 += (double)b;
        q0 += (double)a * (double)a;
        q1 += (double)b * (double)b;
    }
    for (int o = 16; o > 0; o >>= 1) {
        s0 += __shfl_down_sync(0xffffffffu, s0, o);
        s1 += __shfl_down_sync(0xffffffffu, s1, o);
        q0 += __shfl_down_sync(0xffffffffu, q0, o);
        q1 += __shfl_down_sync(0xffffffffu, q1, o);
    }
    if ((threadIdx.x & 31) == 0) {
        atomicAdd(&g_stats[0], s0);
        atomicAdd(&g_stats[1], s1);
        atomicAdd(&g_stats[2], q0);
        atomicAdd(&g_stats[3], q1);
    }
}

__global__ void finalize_kernel() {
    if (threadIdx.x == 0 && blockIdx.x == 0) {
        const double n = (double)E_;
        double v0 = (g_stats[2] - g_stats[0] * g_stats[0] / n) / (n - 1.0);
        double v1 = (g_stats[3] - g_stats[1] * g_stats[1] / n) / (n - 1.0);
        g_norm[0] = (float)(g_stats[0] / n);
        g_norm[1] = (float)(g_stats[1] / n);
        g_norm[2] = (float)(1.0 / sqrt(v0));
        g_norm[3] = (float)(1.0 / sqrt(v1));
    }
}

// ---------------- edge MLP + scatter (1 item/thread, constant weights) ----------
__global__ void __launch_bounds__(256) edge_kernel(
    const float* __restrict__ x, const int* __restrict__ ei,
    const float* __restrict__ ea)
{
    unsigned gid = blockIdx.x * blockDim.x + threadIdx.x;
    if (gid >= (unsigned)(E_) * B_) return;
    int e = gid >> 3;       // edge id
    int b = gid & 7;        // batch id
    int src = ei[e];
    int tgt = ei[E_ + e];

    float xs[D_], xt[D_];
    const float4* ps = (const float4*)(x + (size_t)(b * N_ + src) * D_);
    const float4* pt = (const float4*)(x + (size_t)(b * N_ + tgt) * D_);
#pragma unroll
    for (int q = 0; q < 4; q++) {
        float4 v = ps[q];
        xs[4 * q + 0] = v.x; xs[4 * q + 1] = v.y;
        xs[4 * q + 2] = v.z; xs[4 * q + 3] = v.w;
        float4 w = pt[q];
        xt[4 * q + 0] = w.x; xt[4 * q + 1] = w.y;
        xt[4 * q + 2] = w.z; xt[4 * q + 3] = w.w;
    }

    float speed = fmaf(xs[14], c_wind[2], c_wind[0]);
    float dir   = fmaf(xs[15], c_wind[3], c_wind[1]);
    float cd    = ea[2 * e];
    float cdi   = ea[2 * e + 1];
    float theta = fabsf(cdi - dir);
    float ewt   = fmaxf(0.0f, 3.0f * speed * __cosf(theta) / cd);
    float ean0  = (cd  - g_norm[0]) * g_norm[2];
    float ean1  = (cdi - g_norm[1]) * g_norm[3];

    // ---- layer 1 ----
    float h[EH_];
#pragma unroll
    for (int j = 0; j < EH_; j++) h[j] = c_b1[j];

#pragma unroll
    for (int k = 0; k < D_; k++) {
        float f = xs[k];
#pragma unroll
        for (int j = 0; j < EH_; j++) h[j] = fmaf(f, c_W1[k * EH_ + j], h[j]);
    }
#pragma unroll
    for (int k = 0; k < D_; k++) {
        float f = xt[k];
#pragma unroll
        for (int j = 0; j < EH_; j++) h[j] = fmaf(f, c_W1[(D_ + k) * EH_ + j], h[j]);
    }
#pragma unroll
    for (int j = 0; j < EH_; j++) {
        h[j] = fmaf(ean0, c_W1[32 * EH_ + j],
               fmaf(ean1, c_W1[33 * EH_ + j],
               fmaf(ewt,  c_W1[34 * EH_ + j], h[j])));
    }

#pragma unroll
    for (int j = 0; j < EH_; j++) h[j] = sigmoidf(h[j]);

    // ---- layer 2 (natural W2 [32][30], j-outer accumulation) ----
    float acc[EOUT_];
#pragma unroll
    for (int o = 0; o < EOUT_; o++) acc[o] = c_b2[o];
#pragma unroll
    for (int j = 0; j < EH_; j++) {
        float hj = h[j];
#pragma unroll
        for (int o = 0; o < EOUT_; o++)
            acc[o] = fmaf(hj, c_W2[j * EOUT_ + o], acc[o]);
    }

    float ev[EOUT_];
#pragma unroll
    for (int o = 0; o < EOUT_; o++) ev[o] = sigmoidf(acc[o]);

    // ---- scatter (vector reductions) ----
    float* at = g_agg + (size_t)(b * N_ + tgt) * EOUTP_;
    float* as = g_agg + (size_t)(b * N_ + src) * EOUTP_;
#pragma unroll
    for (int c4 = 0; c4 < 7; c4++) {
        int o0 = 4 * c4;
        red_v4(at + o0,  ev[o0 + 0],  ev[o0 + 1],  ev[o0 + 2],  ev[o0 + 3]);
        red_v4(as + o0, -ev[o0 + 0], -ev[o0 + 1], -ev[o0 + 2], -ev[o0 + 3]);
    }
    red_v2(at + 28,  ev[28],  ev[29]);
    red_v2(as + 28, -ev[28], -ev[29]);
}

// ---------------- node MLP (constant weights) ----------------
__global__ void __launch_bounds__(256) node_kernel(float* __restrict__ out)
{
    int node = blockIdx.x * blockDim.x + threadIdx.x;  // flattened (b, n)
    if (node >= B_ * N_) return;

    float a[EOUT_];
    const float4* ag = (const float4*)(g_agg + (size_t)node * EOUTP_);
#pragma unroll
    for (int q = 0; q < 7; q++) {
        float4 v = ag[q];
        a[4 * q + 0] = v.x; a[4 * q + 1] = v.y;
        a[4 * q + 2] = v.z; a[4 * q + 3] = v.w;
    }
    {
        float4 v = ag[7];
        a[28] = v.x; a[29] = v.y;  // ignore padding .z/.w
    }

    float* op = out + (size_t)node * NOUT_;
#pragma unroll
    for (int o = 0; o < NOUT_; o += 8) {
        float acc[8];
#pragma unroll
        for (int t = 0; t < 8; t++) acc[t] = c_bn[o + t];
#pragma unroll
        for (int j = 0; j < EOUT_; j++) {
            float aj = a[j];
#pragma unroll
            for (int t = 0; t < 8; t++)
                acc[t] = fmaf(aj, c_Wn[j * NOUT_ + o + t], acc[t]);
        }
        float4 r0 = make_float4(sigmoidf(acc[0]), sigmoidf(acc[1]),
                                sigmoidf(acc[2]), sigmoidf(acc[3]));
        float4 r1 = make_float4(sigmoidf(acc[4]), sigmoidf(acc[5]),
                                sigmoidf(acc[6]), sigmoidf(acc[7]));
        *(float4*)(op + o)     = r0;
        *(float4*)(op + o + 4) = r1;
    }
}

// ---------------- launch ----------------
extern "C" void kernel_launch(void* const* d_in, const int* in_sizes, int n_in,
                              void* d_out, int out_size) {
    const float* x  = (const float*)d_in[0];
    const int*   ei = (const int*)d_in[1];
    const float* ea = (const float*)d_in[2];
    const float* wm = (const float*)d_in[3];
    const float* ws = (const float*)d_in[4];
    const float* W1 = (const float*)d_in[5];
    const float* b1 = (const float*)d_in[6];
    const float* W2 = (const float*)d_in[7];
    const float* b2 = (const float*)d_in[8];
    const float* Wn = (const float*)d_in[9];
    const float* bn = (const float*)d_in[10];
    float* out = (float*)d_out;

    // stage weights into constant memory (D2D async copies are capturable)
    cudaMemcpyToSymbolAsync(c_W1, W1, 35 * EH_ * sizeof(float), 0,
                            cudaMemcpyDeviceToDevice, 0);
    cudaMemcpyToSymbolAsync(c_b1, b1, EH_ * sizeof(float), 0,
                            cudaMemcpyDeviceToDevice, 0);
    cudaMemcpyToSymbolAsync(c_W2, W2, EH_ * EOUT_ * sizeof(float), 0,
                            cudaMemcpyDeviceToDevice, 0);
    cudaMemcpyToSymbolAsync(c_b2, b2, EOUT_ * sizeof(float), 0,
                            cudaMemcpyDeviceToDevice, 0);
    cudaMemcpyToSymbolAsync(c_Wn, Wn, EOUT_ * NOUT_ * sizeof(float), 0,
                            cudaMemcpyDeviceToDevice, 0);
    cudaMemcpyToSymbolAsync(c_bn, bn, NOUT_ * sizeof(float), 0,
                            cudaMemcpyDeviceToDevice, 0);
    cudaMemcpyToSymbolAsync(c_wind, wm, 2 * sizeof(float), 0,
                            cudaMemcpyDeviceToDevice, 0);
    cudaMemcpyToSymbolAsync(c_wind, ws, 2 * sizeof(float), 2 * sizeof(float),
                            cudaMemcpyDeviceToDevice, 0);

    zero_kernel<<<512, 256>>>();
    stats_kernel<<<256, 256>>>(ea);
    finalize_kernel<<<1, 32>>>();
    edge_kernel<<<(E_ * B_) / 256, 256>>>(x, ei, ea);
    node_kernel<<<(B_ * N_ + 255) / 256, 256>>>(out);
}